// round 2
// baseline (speedup 1.0000x reference)
#include <cuda_runtime.h>
#include <cuda_bf16.h>
#include <math.h>

// ---------------------------------------------------------------------------
// Llama prefill: T=128 tokens, L=8 layers, D=1024, H=16 heads x DH=64,
// F=2816 ffn, V=32000 vocab. Output: logits[V] for last token (fp32).
// Token-scan-with-KV-cache in the reference == causal batched prefill here.
// ---------------------------------------------------------------------------

#define TT 128
#define DD 1024
#define HH 16
#define DHH 64
#define FF 2816
#define LL 8
#define VV 32000

// -------------------- scratch (device globals; no allocation) --------------
__device__ __align__(16) float g_x[TT * DD];
__device__ __align__(16) float g_hn[TT * DD];
__device__ __align__(16) float g_q[TT * DD];
__device__ __align__(16) float g_k[TT * DD];
__device__ __align__(16) float g_v[TT * DD];
__device__ __align__(16) float g_att[TT * DD];
__device__ __align__(16) float g_gate[TT * FF];
__device__ __align__(16) float g_up[TT * FF];
__device__ __align__(16) float g_act[TT * FF];
__device__ __align__(16) float g_xl[DD];

// -------------------- embedding gather -------------------------------------
__global__ void gather_kernel(const int* __restrict__ ids,
                              const float* __restrict__ emb,
                              float* __restrict__ x) {
    int t = blockIdx.x;
    int row = ids[t];
    const float4* src = (const float4*)(emb + (size_t)row * DD);
    float4* dst = (float4*)(x + (size_t)t * DD);
    for (int i = threadIdx.x; i < DD / 4; i += blockDim.x) dst[i] = src[i];
}

// -------------------- RMSNorm (one block per row) ---------------------------
__global__ __launch_bounds__(256) void rmsnorm_kernel(const float* __restrict__ x,
                                                      const float* __restrict__ w,
                                                      float* __restrict__ out) {
    int t = blockIdx.x;
    const float* xr = x + (size_t)t * DD;
    float vals[4];
    float ss = 0.f;
#pragma unroll
    for (int i = 0; i < 4; i++) {
        vals[i] = xr[threadIdx.x + i * 256];
        ss += vals[i] * vals[i];
    }
#pragma unroll
    for (int off = 16; off; off >>= 1) ss += __shfl_xor_sync(0xffffffffu, ss, off);
    __shared__ float red[8];
    __shared__ float s_inv;
    if ((threadIdx.x & 31) == 0) red[threadIdx.x >> 5] = ss;
    __syncthreads();
    if (threadIdx.x == 0) {
        float tot = 0.f;
#pragma unroll
        for (int i = 0; i < 8; i++) tot += red[i];
        s_inv = rsqrtf(tot * (1.f / (float)DD) + 1e-5f);
    }
    __syncthreads();
    float inv = s_inv;
#pragma unroll
    for (int i = 0; i < 4; i++) {
        int d = threadIdx.x + i * 256;
        out[(size_t)t * DD + d] = vals[i] * inv * w[d];
    }
}

// -------------------- GEMM: C[z] = A @ B[z] (+ resid) -----------------------
// A: [128, K] row-major. B: [K, N] row-major. BM=64 BN=64 BK=16, 128 threads.
// grid = (N/64, 2, nz). blockIdx.z selects (B, C) pair -> batches QKV / gate+up
// into one launch for SM utilization.
__global__ __launch_bounds__(128) void gemm_kernel(
    const float* __restrict__ A,
    const float* __restrict__ B0, const float* __restrict__ B1,
    const float* __restrict__ B2,
    const float* __restrict__ resid,
    float* __restrict__ C0, float* __restrict__ C1, float* __restrict__ C2,
    int N, int K) {
    const int BM = 64, BN = 64, BK = 16;
    __shared__ float As[BK][BM + 1];  // k-major, padded
    __shared__ float Bs[BK][BN];      // unpadded (float4 access)

    const float* B = (blockIdx.z == 0) ? B0 : (blockIdx.z == 1 ? B1 : B2);
    float* C = (blockIdx.z == 0) ? C0 : (blockIdx.z == 1 ? C1 : C2);

    int m0 = blockIdx.y * BM;
    int n0 = blockIdx.x * BN;
    int tid = threadIdx.x;
    int tx = tid & 15;   // col group: cols tx*4 .. tx*4+3
    int ty = tid >> 4;   // row group: rows ty*8 .. ty*8+7

    float acc[8][4];
#pragma unroll
    for (int i = 0; i < 8; i++)
#pragma unroll
        for (int j = 0; j < 4; j++) acc[i][j] = 0.f;

    for (int k0 = 0; k0 < K; k0 += BK) {
        __syncthreads();
        // A tile 64x16 = 256 float4 loads (transpose into k-major smem)
#pragma unroll
        for (int i = 0; i < 2; i++) {
            int f = tid + i * 128;
            int m = f >> 2, kq = f & 3;
            float4 a = *(const float4*)(A + (size_t)(m0 + m) * K + k0 + kq * 4);
            As[kq * 4 + 0][m] = a.x;
            As[kq * 4 + 1][m] = a.y;
            As[kq * 4 + 2][m] = a.z;
            As[kq * 4 + 3][m] = a.w;
        }
        // B tile 16x64 = 256 float4 loads
#pragma unroll
        for (int i = 0; i < 2; i++) {
            int f = tid + i * 128;
            int n4 = f & 15, kr = f >> 4;
            *(float4*)&Bs[kr][n4 * 4] =
                *(const float4*)(B + (size_t)(k0 + kr) * N + n0 + n4 * 4);
        }
        __syncthreads();
#pragma unroll
        for (int kk = 0; kk < BK; kk++) {
            float4 bv = *(const float4*)&Bs[kk][tx * 4];
#pragma unroll
            for (int i = 0; i < 8; i++) {
                float a = As[kk][ty * 8 + i];
                acc[i][0] += a * bv.x;
                acc[i][1] += a * bv.y;
                acc[i][2] += a * bv.z;
                acc[i][3] += a * bv.w;
            }
        }
    }
#pragma unroll
    for (int i = 0; i < 8; i++) {
        int m = m0 + ty * 8 + i;
        int n = n0 + tx * 4;
        float4 r = make_float4(0.f, 0.f, 0.f, 0.f);
        if (resid) r = *(const float4*)(resid + (size_t)m * N + n);
        float4 o;
        o.x = acc[i][0] + r.x;
        o.y = acc[i][1] + r.y;
        o.z = acc[i][2] + r.z;
        o.w = acc[i][3] + r.w;
        *(float4*)(C + (size_t)m * N + n) = o;
    }
}

// -------------------- RoPE (in place on q and k) ----------------------------
__global__ void rope_kernel(float* __restrict__ q, float* __restrict__ k) {
    int idx = blockIdx.x * blockDim.x + threadIdx.x;
    if (idx >= TT * HH * 32) return;
    int i = idx & 31;
    int h = (idx >> 5) & 15;
    int t = idx >> 9;
    float freq = powf(10000.f, -(float)(2 * i) / (float)DHH);
    float ang = (float)t * freq;
    float c, s;
    __sincosf(ang, &s, &c);
    size_t base = (size_t)t * DD + h * DHH;
    float a = q[base + i], b = q[base + i + 32];
    q[base + i] = a * c - b * s;
    q[base + i + 32] = b * c + a * s;
    a = k[base + i];
    b = k[base + i + 32];
    k[base + i] = a * c - b * s;
    k[base + i + 32] = b * c + a * s;
}

// -------------------- causal attention (tiled flash, static 16KB smem) ------
// grid = (4, 16): blockIdx.y = head, blockIdx.x = query tile (32 queries).
// 128 threads = 4 warps; each warp owns 8 queries with online softmax state in
// registers. K/V streamed through 32-row static smem tiles.
__global__ __launch_bounds__(128) void attn_kernel(const float* __restrict__ q,
                                                   const float* __restrict__ k,
                                                   const float* __restrict__ v,
                                                   float* __restrict__ o) {
    int h = blockIdx.y;
    int jb = blockIdx.x;
    __shared__ float Ks[32][64];
    __shared__ float Vs[32][64];

    int warp = threadIdx.x >> 5;
    int lane = threadIdx.x & 31;
    const float scale = 0.125f;  // 1/sqrt(64)

    float q0[8], q1[8], m[8], l[8], a0[8], a1[8];
#pragma unroll
    for (int qi = 0; qi < 8; qi++) {
        int t = jb * 32 + warp * 8 + qi;
        size_t qb = (size_t)t * DD + h * DHH;
        q0[qi] = q[qb + lane];
        q1[qi] = q[qb + lane + 32];
        m[qi] = -1e30f;
        l[qi] = 0.f;
        a0[qi] = 0.f;
        a1[qi] = 0.f;
    }

    for (int tb = 0; tb <= jb; tb++) {
        __syncthreads();
        // load 32x64 K and V tiles as float4 (512 float4 total, 4/thread each)
        for (int idx = threadIdx.x; idx < 32 * 16; idx += 128) {
            int s = idx >> 4, d4 = idx & 15;
            size_t g = (size_t)(tb * 32 + s) * DD + h * DHH + d4 * 4;
            *(float4*)&Ks[s][d4 * 4] = *(const float4*)(k + g);
            *(float4*)&Vs[s][d4 * 4] = *(const float4*)(v + g);
        }
        __syncthreads();

#pragma unroll 4
        for (int s = 0; s < 32; s++) {
            int srow = tb * 32 + s;
            float kv0 = Ks[s][lane], kv1 = Ks[s][lane + 32];
            float vv0 = Vs[s][lane], vv1 = Vs[s][lane + 32];
#pragma unroll
            for (int qi = 0; qi < 8; qi++) {
                int t = jb * 32 + warp * 8 + qi;
                if (srow > t) continue;  // warp-uniform: t depends on warp+qi only
                float p = q0[qi] * kv0 + q1[qi] * kv1;
#pragma unroll
                for (int off = 16; off; off >>= 1)
                    p += __shfl_xor_sync(0xffffffffu, p, off);
                float sc = p * scale;
                float nm = fmaxf(m[qi], sc);
                float corr = __expf(m[qi] - nm);
                float e = __expf(sc - nm);
                l[qi] = l[qi] * corr + e;
                a0[qi] = a0[qi] * corr + e * vv0;
                a1[qi] = a1[qi] * corr + e * vv1;
                m[qi] = nm;
            }
        }
    }

#pragma unroll
    for (int qi = 0; qi < 8; qi++) {
        int t = jb * 32 + warp * 8 + qi;
        size_t qb = (size_t)t * DD + h * DHH;
        float inv = 1.f / l[qi];
        o[qb + lane] = a0[qi] * inv;
        o[qb + lane + 32] = a1[qi] * inv;
    }
}

// -------------------- SwiGLU -------------------------------------------------
__global__ void swiglu_kernel(const float* __restrict__ g,
                              const float* __restrict__ u,
                              float* __restrict__ act) {
    int i = blockIdx.x * blockDim.x + threadIdx.x;
    if (i >= TT * FF) return;
    float gv = g[i];
    float sig = 1.f / (1.f + __expf(-gv));
    act[i] = gv * sig * u[i];
}

// -------------------- lm head: logits[r] = emb[r,:] . xl --------------------
__global__ __launch_bounds__(256) void logits_kernel(const float* __restrict__ emb,
                                                     const float* __restrict__ xl,
                                                     float* __restrict__ out) {
    int row = blockIdx.x * 8 + (threadIdx.x >> 5);
    int lane = threadIdx.x & 31;
    if (row >= VV) return;
    const float4* er = (const float4*)(emb + (size_t)row * DD);
    const float4* xr = (const float4*)xl;
    float s = 0.f;
#pragma unroll 4
    for (int i = lane; i < DD / 4; i += 32) {
        float4 e = er[i];
        float4 x = xr[i];
        s += e.x * x.x + e.y * x.y + e.z * x.z + e.w * x.w;
    }
#pragma unroll
    for (int off = 16; off; off >>= 1) s += __shfl_xor_sync(0xffffffffu, s, off);
    if (lane == 0) out[row] = s;
}

// ---------------------------------------------------------------------------
extern "C" void kernel_launch(void* const* d_in, const int* in_sizes, int n_in,
                              void* d_out, int out_size) {
    (void)in_sizes; (void)n_in; (void)out_size;
    const int* ids = (const int*)d_in[0];
    const float* emb = (const float*)d_in[1];
    const float* Wq = (const float*)d_in[2];
    const float* Wk = (const float*)d_in[3];
    const float* Wv = (const float*)d_in[4];
    const float* Wo = (const float*)d_in[5];
    const float* Wg = (const float*)d_in[6];
    const float* Wu = (const float*)d_in[7];
    const float* Wd = (const float*)d_in[8];
    const float* attn_norm = (const float*)d_in[9];
    const float* ffn_norm = (const float*)d_in[10];
    const float* norm_out = (const float*)d_in[11];
    float* out = (float*)d_out;

    float *x, *hn, *q, *k, *v, *att, *gate, *up, *act, *xl;
    cudaGetSymbolAddress((void**)&x, g_x);
    cudaGetSymbolAddress((void**)&hn, g_hn);
    cudaGetSymbolAddress((void**)&q, g_q);
    cudaGetSymbolAddress((void**)&k, g_k);
    cudaGetSymbolAddress((void**)&v, g_v);
    cudaGetSymbolAddress((void**)&att, g_att);
    cudaGetSymbolAddress((void**)&gate, g_gate);
    cudaGetSymbolAddress((void**)&up, g_up);
    cudaGetSymbolAddress((void**)&act, g_act);
    cudaGetSymbolAddress((void**)&xl, g_xl);

    gather_kernel<<<TT, 256>>>(ids, emb, x);

    for (int l = 0; l < LL; l++) {
        const float* wq = Wq + (size_t)l * DD * DD;
        const float* wk = Wk + (size_t)l * DD * DD;
        const float* wv = Wv + (size_t)l * DD * DD;
        const float* wo = Wo + (size_t)l * DD * DD;
        const float* wg = Wg + (size_t)l * DD * FF;
        const float* wu = Wu + (size_t)l * DD * FF;
        const float* wd = Wd + (size_t)l * FF * DD;

        rmsnorm_kernel<<<TT, 256>>>(x, attn_norm + (size_t)l * DD, hn);

        // fused QKV: grid.z batches the three weight matrices (96 blocks)
        gemm_kernel<<<dim3(DD / 64, 2, 3), 128>>>(hn, wq, wk, wv, nullptr,
                                                  q, k, v, DD, DD);

        rope_kernel<<<(TT * HH * 32 + 255) / 256, 256>>>(q, k);

        attn_kernel<<<dim3(4, HH), 128>>>(q, k, v, att);

        // O projection + residual into x
        gemm_kernel<<<dim3(DD / 64, 2, 1), 128>>>(att, wo, nullptr, nullptr, x,
                                                  x, nullptr, nullptr, DD, DD);

        rmsnorm_kernel<<<TT, 256>>>(x, ffn_norm + (size_t)l * DD, hn);

        // fused gate + up (176 blocks)
        gemm_kernel<<<dim3(FF / 64, 2, 2), 128>>>(hn, wg, wu, nullptr, nullptr,
                                                  gate, up, nullptr, FF, DD);

        swiglu_kernel<<<(TT * FF + 255) / 256, 256>>>(gate, up, act);

        // down projection + residual into x
        gemm_kernel<<<dim3(DD / 64, 2, 1), 128>>>(act, wd, nullptr, nullptr, x,
                                                  x, nullptr, nullptr, DD, FF);
    }

    // final norm on last token only
    rmsnorm_kernel<<<1, 256>>>(x + (size_t)(TT - 1) * DD, norm_out, xl);

    // tied lm head
    logits_kernel<<<(VV + 7) / 8, 256>>>(emb, xl, out);
}

// round 3
// speedup vs baseline: 1.8000x; 1.8000x over previous
#include <cuda_runtime.h>
#include <cuda_bf16.h>
#include <math.h>
#include <stdint.h>

// ---------------------------------------------------------------------------
// Llama prefill: T=128, L=8, D=1024, H=16 x DH=64, F=2816, V=32000.
// Causal batched prefill == reference's token-scan with KV cache.
// GEMMs: bf16 split-precision (hi+lo) tensor-core MMA, fp32 accumulate.
// ---------------------------------------------------------------------------

#define TT 128
#define DD 1024
#define HH 16
#define DHH 64
#define FF 2816
#define LL 8
#define VV 32000

// -------------------- scratch (device globals; no allocation) --------------
__device__ __align__(16) float g_x[TT * DD];
__device__ __align__(16) float g_hn[TT * DD];
__device__ __align__(16) float g_q[TT * DD];
__device__ __align__(16) float g_k[TT * DD];
__device__ __align__(16) float g_v[TT * DD];
__device__ __align__(16) float g_att[TT * DD];
__device__ __align__(16) float g_act[TT * FF];
__device__ __align__(16) float g_p[4 * TT * DD];   // split-K partials
__device__ __align__(16) float g_xl[DD];

// -------------------- MMA helpers ------------------------------------------
__device__ __forceinline__ void ldsm4(uint32_t* r, const __nv_bfloat16* p) {
    uint32_t a = (uint32_t)__cvta_generic_to_shared(p);
    asm volatile("ldmatrix.sync.aligned.m8n8.x4.shared.b16 {%0,%1,%2,%3},[%4];"
                 : "=r"(r[0]), "=r"(r[1]), "=r"(r[2]), "=r"(r[3]) : "r"(a));
}
__device__ __forceinline__ void ldsm4t(uint32_t* r, const __nv_bfloat16* p) {
    uint32_t a = (uint32_t)__cvta_generic_to_shared(p);
    asm volatile("ldmatrix.sync.aligned.m8n8.x4.trans.shared.b16 {%0,%1,%2,%3},[%4];"
                 : "=r"(r[0]), "=r"(r[1]), "=r"(r[2]), "=r"(r[3]) : "r"(a));
}
__device__ __forceinline__ void mma16816(float* c, const uint32_t* a,
                                         const uint32_t b0, const uint32_t b1) {
    asm volatile(
        "mma.sync.aligned.m16n8k16.row.col.f32.bf16.bf16.f32 "
        "{%0,%1,%2,%3},{%4,%5,%6,%7},{%8,%9},{%0,%1,%2,%3};"
        : "+f"(c[0]), "+f"(c[1]), "+f"(c[2]), "+f"(c[3])
        : "r"(a[0]), "r"(a[1]), "r"(a[2]), "r"(a[3]), "r"(b0), "r"(b1));
}

// split fp32 -> bf16 hi + bf16 lo, store 4 at once (8B stores)
__device__ __forceinline__ void split_store4(float4 a, __nv_bfloat16* ph,
                                             __nv_bfloat16* pl) {
    float f[4] = {a.x, a.y, a.z, a.w};
    ushort4 h, l;
    unsigned short* hp = (unsigned short*)&h;
    unsigned short* lp = (unsigned short*)&l;
#pragma unroll
    for (int j = 0; j < 4; j++) {
        __nv_bfloat16 hb = __float2bfloat16(f[j]);
        __nv_bfloat16 lb = __float2bfloat16(f[j] - __bfloat162float(hb));
        hp[j] = __bfloat16_as_ushort(hb);
        lp[j] = __bfloat16_as_ushort(lb);
    }
    *(ushort4*)ph = h;
    *(ushort4*)pl = l;
}

// ---------------------------------------------------------------------------
// gemm_tiles<BN,DUAL>: C(128 x BN) += A(128 x K) @ B(K x N)[n0..n0+BN) over
// k in [kbeg,kend). 256 threads, 8 warps. Split bf16 hi/lo, 3 MMAs per tile.
// Accumulators left in registers for the caller's epilogue.
// ---------------------------------------------------------------------------
template <int BN, bool DUAL>
__device__ __forceinline__ void gemm_tiles(
    const float* __restrict__ A, int lda,
    const float* __restrict__ B0, const float* __restrict__ B1, int ldb, int n0,
    int kbeg, int kend,
    __nv_bfloat16* Ah, __nv_bfloat16* Al,
    __nv_bfloat16* B0h, __nv_bfloat16* B0l,
    __nv_bfloat16* B1h, __nv_bfloat16* B1l,
    float (*accA)[4], float (*accB)[4]) {
    constexpr int WARPS_N = BN / 32;
    constexpr int WARPS_M = 8 / WARPS_N;
    constexpr int WM = 128 / WARPS_M;
    constexpr int MT = WM / 16;
    constexpr int LDA = 40;        // bf16 elems per A row (32 + pad 8)
    constexpr int LDB = BN + 8;    // bf16 elems per B row
    const int tid = threadIdx.x, warp = tid >> 5, lane = tid & 31;
    const int wm = warp / WARPS_N, wn = warp % WARPS_N;

    for (int k0 = kbeg; k0 < kend; k0 += 32) {
        __syncthreads();
        // ---- load + split A tile (128 x 32 fp32) ----
#pragma unroll
        for (int it = 0; it < 4; it++) {
            int idx = tid + it * 256;
            int row = idx >> 3, q = idx & 7;
            float4 a4 = *(const float4*)(A + (size_t)row * lda + k0 + q * 4);
            split_store4(a4, Ah + row * LDA + q * 4, Al + row * LDA + q * 4);
        }
        // ---- load + split B tile(s) (32 x BN fp32, k-major) ----
        constexpr int BV4 = BN / 4;
        constexpr int TOT = 32 * BV4;
#pragma unroll
        for (int it = 0; it < TOT / 256; it++) {
            int idx = tid + it * 256;
            int kk = idx / BV4, n4 = idx % BV4;
            float4 b4 = *(const float4*)(B0 + (size_t)(k0 + kk) * ldb + n0 + n4 * 4);
            split_store4(b4, B0h + kk * LDB + n4 * 4, B0l + kk * LDB + n4 * 4);
            if (DUAL) {
                float4 c4 = *(const float4*)(B1 + (size_t)(k0 + kk) * ldb + n0 + n4 * 4);
                split_store4(c4, B1h + kk * LDB + n4 * 4, B1l + kk * LDB + n4 * 4);
            }
        }
        __syncthreads();
        // ---- MMA over two k16 steps ----
#pragma unroll
        for (int s = 0; s < 2; s++) {
            uint32_t ah[MT][4], al[MT][4];
            int arow = wm * WM + (lane & 15);
            int acol = s * 16 + (lane >> 4) * 8;
#pragma unroll
            for (int mt = 0; mt < MT; mt++) {
                ldsm4(ah[mt], Ah + (arow + mt * 16) * LDA + acol);
                ldsm4(al[mt], Al + (arow + mt * 16) * LDA + acol);
            }
            int brow = s * 16 + (lane & 7) + ((lane >> 3) & 1) * 8;
            int bcol = wn * 32 + (lane >> 4) * 8;
            uint32_t b0h[2][4], b0l[2][4];
#pragma unroll
            for (int p = 0; p < 2; p++) {
                ldsm4t(b0h[p], B0h + brow * LDB + bcol + p * 16);
                ldsm4t(b0l[p], B0l + brow * LDB + bcol + p * 16);
            }
#pragma unroll
            for (int mt = 0; mt < MT; mt++)
#pragma unroll
                for (int nt = 0; nt < 4; nt++) {
                    int p = nt >> 1, o = (nt & 1) * 2;
                    float* c = accA[mt * 4 + nt];
                    mma16816(c, ah[mt], b0h[p][o], b0h[p][o + 1]);
                    mma16816(c, al[mt], b0h[p][o], b0h[p][o + 1]);
                    mma16816(c, ah[mt], b0l[p][o], b0l[p][o + 1]);
                }
            if (DUAL) {
                uint32_t b1h[2][4], b1l[2][4];
#pragma unroll
                for (int p = 0; p < 2; p++) {
                    ldsm4t(b1h[p], B1h + brow * LDB + bcol + p * 16);
                    ldsm4t(b1l[p], B1l + brow * LDB + bcol + p * 16);
                }
#pragma unroll
                for (int mt = 0; mt < MT; mt++)
#pragma unroll
                    for (int nt = 0; nt < 4; nt++) {
                        int p = nt >> 1, o = (nt & 1) * 2;
                        float* c = accB[mt * 4 + nt];
                        mma16816(c, ah[mt], b1h[p][o], b1h[p][o + 1]);
                        mma16816(c, al[mt], b1h[p][o], b1h[p][o + 1]);
                        mma16816(c, ah[mt], b1l[p][o], b1l[p][o + 1]);
                    }
            }
        }
    }
    __syncthreads();  // caller may reuse smem
}

// ---------------------------------------------------------------------------
// QKV GEMM with fused RoPE epilogue. grid = (16, 3): x = head/col tile (BN=64),
// y = matrix (0=q, 1=k, 2=v). hn[128,1024] @ W[1024,1024].
// ---------------------------------------------------------------------------
__global__ __launch_bounds__(256) void qkv_kernel(
    const float* __restrict__ hn,
    const float* __restrict__ Wq, const float* __restrict__ Wk,
    const float* __restrict__ Wv,
    float* __restrict__ q, float* __restrict__ k, float* __restrict__ v) {
    __shared__ __align__(16) char smem_raw[33792];
    __nv_bfloat16* Ah = (__nv_bfloat16*)smem_raw;                 // 128*40
    __nv_bfloat16* Al = Ah + 128 * 40;
    __nv_bfloat16* Bh = Al + 128 * 40;                            // 32*72
    __nv_bfloat16* Bl = Bh + 32 * 72;

    const float* B = (blockIdx.y == 0) ? Wq : (blockIdx.y == 1 ? Wk : Wv);
    float* out = (blockIdx.y == 0) ? q : (blockIdx.y == 1 ? k : v);
    int n0 = blockIdx.x * 64;

    float acc[8][4];
#pragma unroll
    for (int i = 0; i < 8; i++)
#pragma unroll
        for (int j = 0; j < 4; j++) acc[i][j] = 0.f;

    gemm_tiles<64, false>(hn, DD, B, nullptr, DD, n0, 0, DD,
                          Ah, Al, Bh, Bl, nullptr, nullptr, acc, nullptr);

    // stage to smem (fp32, stride 66), then RoPE + coalesced write
    float* cst = (float*)smem_raw;
    int tid = threadIdx.x, warp = tid >> 5, lane = tid & 31;
    int wm = warp >> 1, wn = warp & 1;
#pragma unroll
    for (int mt = 0; mt < 2; mt++)
#pragma unroll
        for (int nt = 0; nt < 4; nt++) {
            int r = wm * 32 + mt * 16 + (lane >> 2);
            int c = wn * 32 + nt * 8 + (lane & 3) * 2;
            cst[r * 66 + c] = acc[mt * 4 + nt][0];
            cst[r * 66 + c + 1] = acc[mt * 4 + nt][1];
            cst[(r + 8) * 66 + c] = acc[mt * 4 + nt][2];
            cst[(r + 8) * 66 + c + 1] = acc[mt * 4 + nt][3];
        }
    __syncthreads();

    int c = tid & 63, rg = tid >> 6;
    int i = c & 31;
    // inv freq = 10000^(-2i/64)
    float invf = expf(-(float)(2 * i) * (9.2103403719761836f / 64.f));
    bool isv = (blockIdx.y == 2);
    for (int rr = 0; rr < 32; rr++) {
        int t = rg * 32 + rr;
        float a = cst[t * 66 + c];
        float val;
        if (isv) {
            val = a;
        } else {
            float b = cst[t * 66 + (c ^ 32)];
            float sn, cs;
            sincosf((float)t * invf, &sn, &cs);
            val = (c < 32) ? (a * cs - b * sn) : (a * cs + b * sn);
        }
        out[(size_t)t * DD + n0 + c] = val;
    }
}

// ---------------------------------------------------------------------------
// Split-K projection GEMM (Wo / Wd). grid = (N/32, S). Writes fp32 partials to
// P + blockIdx.y * TT * N (summed later by addnorm_kernel).
// ---------------------------------------------------------------------------
__global__ __launch_bounds__(256) void proj_kernel(
    const float* __restrict__ A, const float* __restrict__ B,
    float* __restrict__ P, int N, int K, int S) {
    __shared__ __align__(16) char smem_raw[25600];
    __nv_bfloat16* Ah = (__nv_bfloat16*)smem_raw;
    __nv_bfloat16* Al = Ah + 128 * 40;
    __nv_bfloat16* Bh = Al + 128 * 40;   // 32*40
    __nv_bfloat16* Bl = Bh + 32 * 40;

    int n0 = blockIdx.x * 32;
    int kchunk = K / S;
    int kbeg = blockIdx.y * kchunk;

    float acc[4][4];
#pragma unroll
    for (int i = 0; i < 4; i++)
#pragma unroll
        for (int j = 0; j < 4; j++) acc[i][j] = 0.f;

    gemm_tiles<32, false>(A, K, B, nullptr, N, n0, kbeg, kbeg + kchunk,
                          Ah, Al, Bh, Bl, nullptr, nullptr, acc, nullptr);

    float* Pp = P + (size_t)blockIdx.y * TT * N;
    int warp = threadIdx.x >> 5, lane = threadIdx.x & 31;
    int r = warp * 16 + (lane >> 2);
#pragma unroll
    for (int nt = 0; nt < 4; nt++) {
        int c = n0 + nt * 8 + (lane & 3) * 2;
        *(float2*)(Pp + (size_t)r * N + c) = make_float2(acc[nt][0], acc[nt][1]);
        *(float2*)(Pp + (size_t)(r + 8) * N + c) = make_float2(acc[nt][2], acc[nt][3]);
    }
}

// ---------------------------------------------------------------------------
// Gate+Up dual GEMM with fused SwiGLU. grid = (FF/32). act = silu(g) * u.
// ---------------------------------------------------------------------------
__global__ __launch_bounds__(256) void gateup_kernel(
    const float* __restrict__ hn, const float* __restrict__ Wg,
    const float* __restrict__ Wu, float* __restrict__ act) {
    __shared__ __align__(16) char smem_raw[30720];
    __nv_bfloat16* Ah = (__nv_bfloat16*)smem_raw;
    __nv_bfloat16* Al = Ah + 128 * 40;
    __nv_bfloat16* B0h = Al + 128 * 40;
    __nv_bfloat16* B0l = B0h + 32 * 40;
    __nv_bfloat16* B1h = B0l + 32 * 40;
    __nv_bfloat16* B1l = B1h + 32 * 40;

    int n0 = blockIdx.x * 32;
    float accA[4][4], accB[4][4];
#pragma unroll
    for (int i = 0; i < 4; i++)
#pragma unroll
        for (int j = 0; j < 4; j++) { accA[i][j] = 0.f; accB[i][j] = 0.f; }

    gemm_tiles<32, true>(hn, DD, Wg, Wu, FF, n0, 0, DD,
                         Ah, Al, B0h, B0l, B1h, B1l, accA, accB);

    int warp = threadIdx.x >> 5, lane = threadIdx.x & 31;
    int r = warp * 16 + (lane >> 2);
#pragma unroll
    for (int nt = 0; nt < 4; nt++) {
        int c = n0 + nt * 8 + (lane & 3) * 2;
#pragma unroll
        for (int half = 0; half < 2; half++) {
            float g0 = accA[nt][half * 2 + 0], g1 = accA[nt][half * 2 + 1];
            float u0 = accB[nt][half * 2 + 0], u1 = accB[nt][half * 2 + 1];
            float r0 = g0 / (1.f + expf(-g0)) * u0;
            float r1 = g1 / (1.f + expf(-g1)) * u1;
            *(float2*)(act + (size_t)(r + half * 8) * FF + c) = make_float2(r0, r1);
        }
    }
}

// ---------------------------------------------------------------------------
// x[t] += sum_s parts[s][t]; hn_out[row] = rmsnorm(x[t]) * w.
// grid = (#rows); t = row0 + blockIdx.x; out indexed by blockIdx.x.
// ---------------------------------------------------------------------------
__global__ __launch_bounds__(256) void addnorm_kernel(
    float* __restrict__ x, const float* __restrict__ parts, int S,
    const float* __restrict__ w, float* __restrict__ out, int row0) {
    int t = row0 + blockIdx.x;
    float vals[4];
    float ss = 0.f;
#pragma unroll
    for (int i = 0; i < 4; i++) {
        int d = threadIdx.x + i * 256;
        float v = x[(size_t)t * DD + d];
        for (int s = 0; s < S; s++) v += parts[(size_t)s * TT * DD + (size_t)t * DD + d];
        vals[i] = v;
        ss += v * v;
    }
    if (S)
#pragma unroll
        for (int i = 0; i < 4; i++) x[(size_t)t * DD + threadIdx.x + i * 256] = vals[i];
#pragma unroll
    for (int off = 16; off; off >>= 1) ss += __shfl_xor_sync(0xffffffffu, ss, off);
    __shared__ float red[8];
    __shared__ float s_inv;
    if ((threadIdx.x & 31) == 0) red[threadIdx.x >> 5] = ss;
    __syncthreads();
    if (threadIdx.x == 0) {
        float tot = 0.f;
#pragma unroll
        for (int i = 0; i < 8; i++) tot += red[i];
        s_inv = rsqrtf(tot * (1.f / (float)DD) + 1e-5f);
    }
    __syncthreads();
    float inv = s_inv;
#pragma unroll
    for (int i = 0; i < 4; i++) {
        int d = threadIdx.x + i * 256;
        out[(size_t)blockIdx.x * DD + d] = vals[i] * inv * w[d];
    }
}

// -------------------- embedding gather -------------------------------------
__global__ void gather_kernel(const int* __restrict__ ids,
                              const float* __restrict__ emb,
                              float* __restrict__ x) {
    int t = blockIdx.x;
    int row = ids[t];
    const float4* src = (const float4*)(emb + (size_t)row * DD);
    float4* dst = (float4*)(x + (size_t)t * DD);
    for (int i = threadIdx.x; i < DD / 4; i += blockDim.x) dst[i] = src[i];
}

// -------------------- causal attention (unchanged from R2, passing) ---------
__global__ __launch_bounds__(128) void attn_kernel(const float* __restrict__ q,
                                                   const float* __restrict__ k,
                                                   const float* __restrict__ v,
                                                   float* __restrict__ o) {
    int h = blockIdx.y;
    int jb = blockIdx.x;
    __shared__ float Ks[32][64];
    __shared__ float Vs[32][64];

    int warp = threadIdx.x >> 5;
    int lane = threadIdx.x & 31;
    const float scale = 0.125f;

    float q0[8], q1[8], m[8], l[8], a0[8], a1[8];
#pragma unroll
    for (int qi = 0; qi < 8; qi++) {
        int t = jb * 32 + warp * 8 + qi;
        size_t qb = (size_t)t * DD + h * DHH;
        q0[qi] = q[qb + lane];
        q1[qi] = q[qb + lane + 32];
        m[qi] = -1e30f;
        l[qi] = 0.f;
        a0[qi] = 0.f;
        a1[qi] = 0.f;
    }

    for (int tb = 0; tb <= jb; tb++) {
        __syncthreads();
        for (int idx = threadIdx.x; idx < 32 * 16; idx += 128) {
            int s = idx >> 4, d4 = idx & 15;
            size_t g = (size_t)(tb * 32 + s) * DD + h * DHH + d4 * 4;
            *(float4*)&Ks[s][d4 * 4] = *(const float4*)(k + g);
            *(float4*)&Vs[s][d4 * 4] = *(const float4*)(v + g);
        }
        __syncthreads();

#pragma unroll 4
        for (int s = 0; s < 32; s++) {
            int srow = tb * 32 + s;
            float kv0 = Ks[s][lane], kv1 = Ks[s][lane + 32];
            float vv0 = Vs[s][lane], vv1 = Vs[s][lane + 32];
#pragma unroll
            for (int qi = 0; qi < 8; qi++) {
                int t = jb * 32 + warp * 8 + qi;
                if (srow > t) continue;
                float p = q0[qi] * kv0 + q1[qi] * kv1;
#pragma unroll
                for (int off = 16; off; off >>= 1)
                    p += __shfl_xor_sync(0xffffffffu, p, off);
                float sc = p * scale;
                float nm = fmaxf(m[qi], sc);
                float corr = __expf(m[qi] - nm);
                float e = __expf(sc - nm);
                l[qi] = l[qi] * corr + e;
                a0[qi] = a0[qi] * corr + e * vv0;
                a1[qi] = a1[qi] * corr + e * vv1;
                m[qi] = nm;
            }
        }
    }

#pragma unroll
    for (int qi = 0; qi < 8; qi++) {
        int t = jb * 32 + warp * 8 + qi;
        size_t qb = (size_t)t * DD + h * DHH;
        float inv = 1.f / l[qi];
        o[qb + lane] = a0[qi] * inv;
        o[qb + lane + 32] = a1[qi] * inv;
    }
}

// -------------------- lm head -----------------------------------------------
__global__ __launch_bounds__(256) void logits_kernel(const float* __restrict__ emb,
                                                     const float* __restrict__ xl,
                                                     float* __restrict__ out) {
    int row = blockIdx.x * 8 + (threadIdx.x >> 5);
    int lane = threadIdx.x & 31;
    if (row >= VV) return;
    const float4* er = (const float4*)(emb + (size_t)row * DD);
    const float4* xr = (const float4*)xl;
    float s = 0.f;
#pragma unroll 4
    for (int i = lane; i < DD / 4; i += 32) {
        float4 e = er[i];
        float4 x = xr[i];
        s += e.x * x.x + e.y * x.y + e.z * x.z + e.w * x.w;
    }
#pragma unroll
    for (int off = 16; off; off >>= 1) s += __shfl_xor_sync(0xffffffffu, s, off);
    if (lane == 0) out[row] = s;
}

// ---------------------------------------------------------------------------
extern "C" void kernel_launch(void* const* d_in, const int* in_sizes, int n_in,
                              void* d_out, int out_size) {
    (void)in_sizes; (void)n_in; (void)out_size;
    const int* ids = (const int*)d_in[0];
    const float* emb = (const float*)d_in[1];
    const float* Wq = (const float*)d_in[2];
    const float* Wk = (const float*)d_in[3];
    const float* Wv = (const float*)d_in[4];
    const float* Wo = (const float*)d_in[5];
    const float* Wg = (const float*)d_in[6];
    const float* Wu = (const float*)d_in[7];
    const float* Wd = (const float*)d_in[8];
    const float* attn_norm = (const float*)d_in[9];
    const float* ffn_norm = (const float*)d_in[10];
    const float* norm_out = (const float*)d_in[11];
    float* out = (float*)d_out;

    float *x, *hn, *q, *k, *v, *att, *act, *p, *xl;
    cudaGetSymbolAddress((void**)&x, g_x);
    cudaGetSymbolAddress((void**)&hn, g_hn);
    cudaGetSymbolAddress((void**)&q, g_q);
    cudaGetSymbolAddress((void**)&k, g_k);
    cudaGetSymbolAddress((void**)&v, g_v);
    cudaGetSymbolAddress((void**)&att, g_att);
    cudaGetSymbolAddress((void**)&act, g_act);
    cudaGetSymbolAddress((void**)&p, g_p);
    cudaGetSymbolAddress((void**)&xl, g_xl);

    gather_kernel<<<TT, 256>>>(ids, emb, x);

    for (int l = 0; l < LL; l++) {
        const float* wq = Wq + (size_t)l * DD * DD;
        const float* wk = Wk + (size_t)l * DD * DD;
        const float* wv = Wv + (size_t)l * DD * DD;
        const float* wo = Wo + (size_t)l * DD * DD;
        const float* wg = Wg + (size_t)l * DD * FF;
        const float* wu = Wu + (size_t)l * DD * FF;
        const float* wd = Wd + (size_t)l * FF * DD;

        // x += previous layer's down-proj partials (S=4), then attn rmsnorm
        addnorm_kernel<<<TT, 256>>>(x, p, (l == 0) ? 0 : 4,
                                    attn_norm + (size_t)l * DD, hn, 0);

        qkv_kernel<<<dim3(16, 3), 256>>>(hn, wq, wk, wv, q, k, v);

        attn_kernel<<<dim3(4, HH), 128>>>(q, k, v, att);

        // O projection split-K=4 -> partials
        proj_kernel<<<dim3(32, 4), 256>>>(att, wo, p, DD, DD, 4);

        // x += Wo partials, ffn rmsnorm
        addnorm_kernel<<<TT, 256>>>(x, p, 4, ffn_norm + (size_t)l * DD, hn, 0);

        // gate+up fused with SwiGLU
        gateup_kernel<<<FF / 32, 256>>>(hn, wg, wu, act);

        // down projection split-K=4 -> partials (consumed by next addnorm)
        proj_kernel<<<dim3(32, 4), 256>>>(act, wd, p, DD, FF, 4);
    }

    // final: x[127] += down partials, norm -> xl
    addnorm_kernel<<<1, 256>>>(x, p, 4, norm_out, xl, TT - 1);

    logits_kernel<<<(VV + 7) / 8, 256>>>(emb, xl, out);
}

// round 6
// speedup vs baseline: 3.1814x; 1.7675x over previous
#include <cuda_runtime.h>
#include <cuda_bf16.h>
#include <math.h>
#include <stdint.h>

// ---------------------------------------------------------------------------
// Llama prefill: T=128, L=8, D=1024, H=16 x DH=64, F=2816, V=32000.
// Causal batched prefill == reference's token-scan with KV cache.
// GEMMs: bf16 split-precision (hi+lo) tensor-core MMA, fp32 accumulate.
// ---------------------------------------------------------------------------

#define TT 128
#define DD 1024
#define HH 16
#define DHH 64
#define FF 2816
#define LL 8
#define VV 32000

// -------------------- scratch (device globals; no allocation) --------------
__device__ __align__(16) float g_x[TT * DD];
__device__ __align__(16) float g_hn[TT * DD];
__device__ __align__(16) float g_q[TT * DD];
__device__ __align__(16) float g_k[TT * DD];
__device__ __align__(16) float g_v[TT * DD];
__device__ __align__(16) float g_att[TT * DD];
__device__ __align__(16) float g_act[TT * FF];
__device__ __align__(16) float g_p[4 * TT * DD];   // split-K partials
__device__ __align__(16) float g_xl[DD];

// -------------------- MMA helpers ------------------------------------------
__device__ __forceinline__ void ldsm4(uint32_t* r, const __nv_bfloat16* p) {
    uint32_t a = (uint32_t)__cvta_generic_to_shared(p);
    asm volatile("ldmatrix.sync.aligned.m8n8.x4.shared.b16 {%0,%1,%2,%3},[%4];"
                 : "=r"(r[0]), "=r"(r[1]), "=r"(r[2]), "=r"(r[3]) : "r"(a));
}
__device__ __forceinline__ void ldsm4t(uint32_t* r, const __nv_bfloat16* p) {
    uint32_t a = (uint32_t)__cvta_generic_to_shared(p);
    asm volatile("ldmatrix.sync.aligned.m8n8.x4.trans.shared.b16 {%0,%1,%2,%3},[%4];"
                 : "=r"(r[0]), "=r"(r[1]), "=r"(r[2]), "=r"(r[3]) : "r"(a));
}
__device__ __forceinline__ void mma16816(float* c, const uint32_t* a,
                                         const uint32_t b0, const uint32_t b1) {
    asm volatile(
        "mma.sync.aligned.m16n8k16.row.col.f32.bf16.bf16.f32 "
        "{%0,%1,%2,%3},{%4,%5,%6,%7},{%8,%9},{%0,%1,%2,%3};"
        : "+f"(c[0]), "+f"(c[1]), "+f"(c[2]), "+f"(c[3])
        : "r"(a[0]), "r"(a[1]), "r"(a[2]), "r"(a[3]), "r"(b0), "r"(b1));
}

// split fp32 -> bf16 hi + bf16 lo, store 4 at once (8B stores)
__device__ __forceinline__ void split_store4(float4 a, __nv_bfloat16* ph,
                                             __nv_bfloat16* pl) {
    float f[4] = {a.x, a.y, a.z, a.w};
    ushort4 h, l;
    unsigned short* hp = (unsigned short*)&h;
    unsigned short* lp = (unsigned short*)&l;
#pragma unroll
    for (int j = 0; j < 4; j++) {
        __nv_bfloat16 hb = __float2bfloat16(f[j]);
        __nv_bfloat16 lb = __float2bfloat16(f[j] - __bfloat162float(hb));
        hp[j] = __bfloat16_as_ushort(hb);
        lp[j] = __bfloat16_as_ushort(lb);
    }
    *(ushort4*)ph = h;
    *(ushort4*)pl = l;
}

// ---------------------------------------------------------------------------
// gemm_tiles<BN,DUAL>: C(128 x BN) += A(128 x K) @ B(K x N)[n0..n0+BN) over
// k in [kbeg,kend). 256 threads, 8 warps. Split bf16 hi/lo, 3 MMAs per tile.
// ---------------------------------------------------------------------------
template <int BN, bool DUAL>
__device__ __forceinline__ void gemm_tiles(
    const float* __restrict__ A, int lda,
    const float* __restrict__ B0, const float* __restrict__ B1, int ldb, int n0,
    int kbeg, int kend,
    __nv_bfloat16* Ah, __nv_bfloat16* Al,
    __nv_bfloat16* B0h, __nv_bfloat16* B0l,
    __nv_bfloat16* B1h, __nv_bfloat16* B1l,
    float (*accA)[4], float (*accB)[4]) {
    constexpr int WARPS_N = BN / 32;
    constexpr int WARPS_M = 8 / WARPS_N;
    constexpr int WM = 128 / WARPS_M;
    constexpr int MT = WM / 16;
    constexpr int LDA = 40;        // bf16 elems per A row (32 + pad 8)
    constexpr int LDB = BN + 8;    // bf16 elems per B row
    const int tid = threadIdx.x, warp = tid >> 5, lane = tid & 31;
    const int wm = warp / WARPS_N, wn = warp % WARPS_N;

    for (int k0 = kbeg; k0 < kend; k0 += 32) {
        __syncthreads();
        // ---- load + split A tile (128 x 32 fp32) ----
#pragma unroll
        for (int it = 0; it < 4; it++) {
            int idx = tid + it * 256;
            int row = idx >> 3, q = idx & 7;
            float4 a4 = *(const float4*)(A + (size_t)row * lda + k0 + q * 4);
            split_store4(a4, Ah + row * LDA + q * 4, Al + row * LDA + q * 4);
        }
        // ---- load + split B tile(s) (32 x BN fp32, k-major) ----
        constexpr int BV4 = BN / 4;
        constexpr int TOT = 32 * BV4;
#pragma unroll
        for (int it = 0; it < TOT / 256; it++) {
            int idx = tid + it * 256;
            int kk = idx / BV4, n4 = idx % BV4;
            float4 b4 = *(const float4*)(B0 + (size_t)(k0 + kk) * ldb + n0 + n4 * 4);
            split_store4(b4, B0h + kk * LDB + n4 * 4, B0l + kk * LDB + n4 * 4);
            if (DUAL) {
                float4 c4 = *(const float4*)(B1 + (size_t)(k0 + kk) * ldb + n0 + n4 * 4);
                split_store4(c4, B1h + kk * LDB + n4 * 4, B1l + kk * LDB + n4 * 4);
            }
        }
        __syncthreads();
        // ---- MMA over two k16 steps ----
#pragma unroll
        for (int s = 0; s < 2; s++) {
            uint32_t ah[MT][4], al[MT][4];
            int arow = wm * WM + (lane & 15);
            int acol = s * 16 + (lane >> 4) * 8;
#pragma unroll
            for (int mt = 0; mt < MT; mt++) {
                ldsm4(ah[mt], Ah + (arow + mt * 16) * LDA + acol);
                ldsm4(al[mt], Al + (arow + mt * 16) * LDA + acol);
            }
            int brow = s * 16 + (lane & 7) + ((lane >> 3) & 1) * 8;
            int bcol = wn * 32 + (lane >> 4) * 8;
            uint32_t b0h[2][4], b0l[2][4];
#pragma unroll
            for (int p = 0; p < 2; p++) {
                ldsm4t(b0h[p], B0h + brow * LDB + bcol + p * 16);
                ldsm4t(b0l[p], B0l + brow * LDB + bcol + p * 16);
            }
#pragma unroll
            for (int mt = 0; mt < MT; mt++)
#pragma unroll
                for (int nt = 0; nt < 4; nt++) {
                    int p = nt >> 1, o = (nt & 1) * 2;
                    float* c = accA[mt * 4 + nt];
                    mma16816(c, ah[mt], b0h[p][o], b0h[p][o + 1]);
                    mma16816(c, al[mt], b0h[p][o], b0h[p][o + 1]);
                    mma16816(c, ah[mt], b0l[p][o], b0l[p][o + 1]);
                }
            if (DUAL) {
                uint32_t b1h[2][4], b1l[2][4];
#pragma unroll
                for (int p = 0; p < 2; p++) {
                    ldsm4t(b1h[p], B1h + brow * LDB + bcol + p * 16);
                    ldsm4t(b1l[p], B1l + brow * LDB + bcol + p * 16);
                }
#pragma unroll
                for (int mt = 0; mt < MT; mt++)
#pragma unroll
                    for (int nt = 0; nt < 4; nt++) {
                        int p = nt >> 1, o = (nt & 1) * 2;
                        float* c = accB[mt * 4 + nt];
                        mma16816(c, ah[mt], b1h[p][o], b1h[p][o + 1]);
                        mma16816(c, al[mt], b1h[p][o], b1h[p][o + 1]);
                        mma16816(c, ah[mt], b1l[p][o], b1l[p][o + 1]);
                    }
            }
        }
    }
    __syncthreads();  // caller may reuse smem
}

// ---------------------------------------------------------------------------
// QKV GEMM with fused RoPE epilogue. grid = (16, 3).
// ---------------------------------------------------------------------------
__global__ __launch_bounds__(256) void qkv_kernel(
    const float* __restrict__ hn,
    const float* __restrict__ Wq, const float* __restrict__ Wk,
    const float* __restrict__ Wv,
    float* __restrict__ q, float* __restrict__ k, float* __restrict__ v) {
    __shared__ __align__(16) char smem_raw[33792];
    __nv_bfloat16* Ah = (__nv_bfloat16*)smem_raw;                 // 128*40
    __nv_bfloat16* Al = Ah + 128 * 40;
    __nv_bfloat16* Bh = Al + 128 * 40;                            // 32*72
    __nv_bfloat16* Bl = Bh + 32 * 72;

    const float* B = (blockIdx.y == 0) ? Wq : (blockIdx.y == 1 ? Wk : Wv);
    float* out = (blockIdx.y == 0) ? q : (blockIdx.y == 1 ? k : v);
    int n0 = blockIdx.x * 64;

    float acc[8][4];
#pragma unroll
    for (int i = 0; i < 8; i++)
#pragma unroll
        for (int j = 0; j < 4; j++) acc[i][j] = 0.f;

    gemm_tiles<64, false>(hn, DD, B, nullptr, DD, n0, 0, DD,
                          Ah, Al, Bh, Bl, nullptr, nullptr, acc, nullptr);

    // stage to smem (fp32, stride 66), then RoPE + coalesced write
    float* cst = (float*)smem_raw;
    int tid = threadIdx.x, warp = tid >> 5, lane = tid & 31;
    int wm = warp >> 1, wn = warp & 1;
#pragma unroll
    for (int mt = 0; mt < 2; mt++)
#pragma unroll
        for (int nt = 0; nt < 4; nt++) {
            int r = wm * 32 + mt * 16 + (lane >> 2);
            int c = wn * 32 + nt * 8 + (lane & 3) * 2;
            cst[r * 66 + c] = acc[mt * 4 + nt][0];
            cst[r * 66 + c + 1] = acc[mt * 4 + nt][1];
            cst[(r + 8) * 66 + c] = acc[mt * 4 + nt][2];
            cst[(r + 8) * 66 + c + 1] = acc[mt * 4 + nt][3];
        }
    __syncthreads();

    int c = tid & 63, rg = tid >> 6;
    int i = c & 31;
    float invf = __expf(-(float)(2 * i) * (9.2103403719761836f / 64.f));
    bool isv = (blockIdx.y == 2);
    for (int rr = 0; rr < 32; rr++) {
        int t = rg * 32 + rr;
        float a = cst[t * 66 + c];
        float val;
        if (isv) {
            val = a;
        } else {
            float b = cst[t * 66 + (c ^ 32)];
            float sn, cs;
            __sincosf((float)t * invf, &sn, &cs);
            val = (c < 32) ? (a * cs - b * sn) : (a * cs + b * sn);
        }
        out[(size_t)t * DD + n0 + c] = val;
    }
}

// ---------------------------------------------------------------------------
// Split-K projection GEMM (Wo / Wd). grid = (N/32, S).
// ---------------------------------------------------------------------------
__global__ __launch_bounds__(256) void proj_kernel(
    const float* __restrict__ A, const float* __restrict__ B,
    float* __restrict__ P, int N, int K, int S) {
    __shared__ __align__(16) char smem_raw[25600];
    __nv_bfloat16* Ah = (__nv_bfloat16*)smem_raw;
    __nv_bfloat16* Al = Ah + 128 * 40;
    __nv_bfloat16* Bh = Al + 128 * 40;
    __nv_bfloat16* Bl = Bh + 32 * 40;

    int n0 = blockIdx.x * 32;
    int kchunk = K / S;
    int kbeg = blockIdx.y * kchunk;

    float acc[4][4];
#pragma unroll
    for (int i = 0; i < 4; i++)
#pragma unroll
        for (int j = 0; j < 4; j++) acc[i][j] = 0.f;

    gemm_tiles<32, false>(A, K, B, nullptr, N, n0, kbeg, kbeg + kchunk,
                          Ah, Al, Bh, Bl, nullptr, nullptr, acc, nullptr);

    float* Pp = P + (size_t)blockIdx.y * TT * N;
    int warp = threadIdx.x >> 5, lane = threadIdx.x & 31;
    int r = warp * 16 + (lane >> 2);
#pragma unroll
    for (int nt = 0; nt < 4; nt++) {
        int c = n0 + nt * 8 + (lane & 3) * 2;
        *(float2*)(Pp + (size_t)r * N + c) = make_float2(acc[nt][0], acc[nt][1]);
        *(float2*)(Pp + (size_t)(r + 8) * N + c) = make_float2(acc[nt][2], acc[nt][3]);
    }
}

// ---------------------------------------------------------------------------
// Gate+Up dual GEMM with fused SwiGLU. grid = (FF/32).
// ---------------------------------------------------------------------------
__global__ __launch_bounds__(256) void gateup_kernel(
    const float* __restrict__ hn, const float* __restrict__ Wg,
    const float* __restrict__ Wu, float* __restrict__ act) {
    __shared__ __align__(16) char smem_raw[30720];
    __nv_bfloat16* Ah = (__nv_bfloat16*)smem_raw;
    __nv_bfloat16* Al = Ah + 128 * 40;
    __nv_bfloat16* B0h = Al + 128 * 40;
    __nv_bfloat16* B0l = B0h + 32 * 40;
    __nv_bfloat16* B1h = B0l + 32 * 40;
    __nv_bfloat16* B1l = B1h + 32 * 40;

    int n0 = blockIdx.x * 32;
    float accA[4][4], accB[4][4];
#pragma unroll
    for (int i = 0; i < 4; i++)
#pragma unroll
        for (int j = 0; j < 4; j++) { accA[i][j] = 0.f; accB[i][j] = 0.f; }

    gemm_tiles<32, true>(hn, DD, Wg, Wu, FF, n0, 0, DD,
                         Ah, Al, B0h, B0l, B1h, B1l, accA, accB);

    int warp = threadIdx.x >> 5, lane = threadIdx.x & 31;
    int r = warp * 16 + (lane >> 2);
#pragma unroll
    for (int nt = 0; nt < 4; nt++) {
        int c = n0 + nt * 8 + (lane & 3) * 2;
#pragma unroll
        for (int half = 0; half < 2; half++) {
            float g0 = accA[nt][half * 2 + 0], g1 = accA[nt][half * 2 + 1];
            float u0 = accB[nt][half * 2 + 0], u1 = accB[nt][half * 2 + 1];
            float r0 = g0 / (1.f + __expf(-g0)) * u0;
            float r1 = g1 / (1.f + __expf(-g1)) * u1;
            *(float2*)(act + (size_t)(r + half * 8) * FF + c) = make_float2(r0, r1);
        }
    }
}

// ---------------------------------------------------------------------------
// x[t] += sum_s parts[s][t]; out[blockIdx.x] = rmsnorm(x[t]) * w.
// ---------------------------------------------------------------------------
__global__ __launch_bounds__(256) void addnorm_kernel(
    float* __restrict__ x, const float* __restrict__ parts, int S,
    const float* __restrict__ w, float* __restrict__ out, int row0) {
    int t = row0 + blockIdx.x;
    float vals[4];
    float ss = 0.f;
#pragma unroll
    for (int i = 0; i < 4; i++) {
        int d = threadIdx.x + i * 256;
        float v = x[(size_t)t * DD + d];
        for (int s = 0; s < S; s++) v += parts[(size_t)s * TT * DD + (size_t)t * DD + d];
        vals[i] = v;
        ss += v * v;
    }
    if (S)
#pragma unroll
        for (int i = 0; i < 4; i++) x[(size_t)t * DD + threadIdx.x + i * 256] = vals[i];
#pragma unroll
    for (int off = 16; off; off >>= 1) ss += __shfl_xor_sync(0xffffffffu, ss, off);
    __shared__ float red[8];
    __shared__ float s_inv;
    if ((threadIdx.x & 31) == 0) red[threadIdx.x >> 5] = ss;
    __syncthreads();
    if (threadIdx.x == 0) {
        float tot = 0.f;
#pragma unroll
        for (int i = 0; i < 8; i++) tot += red[i];
        s_inv = rsqrtf(tot * (1.f / (float)DD) + 1e-5f);
    }
    __syncthreads();
    float inv = s_inv;
#pragma unroll
    for (int i = 0; i < 4; i++) {
        int d = threadIdx.x + i * 256;
        out[(size_t)blockIdx.x * DD + d] = vals[i] * inv * w[d];
    }
}

// -------------------- embedding gather -------------------------------------
__global__ void gather_kernel(const int* __restrict__ ids,
                              const float* __restrict__ emb,
                              float* __restrict__ x) {
    int t = blockIdx.x;
    int row = ids[t];
    const float4* src = (const float4*)(emb + (size_t)row * DD);
    float4* dst = (float4*)(x + (size_t)t * DD);
    for (int i = threadIdx.x; i < DD / 4; i += blockDim.x) dst[i] = src[i];
}

// ---------------------------------------------------------------------------
// Causal attention v2: lane-per-key. grid = (8 qtiles x 16 heads) = 128 blocks,
// 128 threads = 4 warps x 4 queries. Scores for 32 keys in parallel (1/lane),
// warp reductions once per 32-key tile, PV via shfl.idx broadcast.
// ---------------------------------------------------------------------------
__global__ __launch_bounds__(128) void attn_kernel(const float* __restrict__ q,
                                                   const float* __restrict__ k,
                                                   const float* __restrict__ v,
                                                   float* __restrict__ o) {
    int h = blockIdx.y;
    int qt = blockIdx.x;               // queries qt*16 .. qt*16+15
    __shared__ float Qs[16][68];
    __shared__ float Ks[32][68];
    __shared__ float Vs[32][68];

    int tid = threadIdx.x, warp = tid >> 5, lane = tid & 31;
    const float scale = 0.125f;

    // load Q tile (16 x 64)
    for (int idx = tid; idx < 16 * 16; idx += 128) {
        int r = idx >> 4, c4 = idx & 15;
        *(float4*)&Qs[r][c4 * 4] =
            *(const float4*)(q + (size_t)(qt * 16 + r) * DD + h * DHH + c4 * 4);
    }

    float m[4], l[4], o0[4], o1[4];
#pragma unroll
    for (int qi = 0; qi < 4; qi++) {
        m[qi] = -1e30f; l[qi] = 0.f; o0[qi] = 0.f; o1[qi] = 0.f;
    }

    int ntiles = (qt * 16 + 15) / 32 + 1;
    for (int tb = 0; tb < ntiles; tb++) {
        __syncthreads();
        for (int idx = tid; idx < 32 * 16; idx += 128) {
            int r = idx >> 4, c4 = idx & 15;
            size_t g = (size_t)(tb * 32 + r) * DD + h * DHH + c4 * 4;
            *(float4*)&Ks[r][c4 * 4] = *(const float4*)(k + g);
            *(float4*)&Vs[r][c4 * 4] = *(const float4*)(v + g);
        }
        __syncthreads();

        // scores: lane owns key tb*32+lane, 4 queries at once
        float p[4] = {0.f, 0.f, 0.f, 0.f};
#pragma unroll
        for (int i = 0; i < 16; i++) {
            float4 kk = *(float4*)&Ks[lane][i * 4];
#pragma unroll
            for (int qi = 0; qi < 4; qi++) {
                float4 qq = *(float4*)&Qs[warp * 4 + qi][i * 4];
                p[qi] += qq.x * kk.x + qq.y * kk.y + qq.z * kk.z + qq.w * kk.w;
            }
        }
        int key = tb * 32 + lane;
#pragma unroll
        for (int qi = 0; qi < 4; qi++) {
            int t = qt * 16 + warp * 4 + qi;
            float sc = (key <= t) ? p[qi] * scale : -1e30f;
            float mx = sc;
#pragma unroll
            for (int off = 16; off; off >>= 1)
                mx = fmaxf(mx, __shfl_xor_sync(0xffffffffu, mx, off));
            float nm = fmaxf(m[qi], mx);
            float e = __expf(sc - nm);
            float sum = e;
#pragma unroll
            for (int off = 16; off; off >>= 1)
                sum += __shfl_xor_sync(0xffffffffu, sum, off);
            float corr = __expf(m[qi] - nm);
            l[qi] = l[qi] * corr + sum;
            m[qi] = nm;
            // PV: broadcast e from each lane
            float a0 = 0.f, a1 = 0.f;
#pragma unroll
            for (int s = 0; s < 32; s++) {
                float es = __shfl_sync(0xffffffffu, e, s);
                a0 += es * Vs[s][lane];
                a1 += es * Vs[s][lane + 32];
            }
            o0[qi] = o0[qi] * corr + a0;
            o1[qi] = o1[qi] * corr + a1;
        }
    }

#pragma unroll
    for (int qi = 0; qi < 4; qi++) {
        int t = qt * 16 + warp * 4 + qi;
        size_t ob = (size_t)t * DD + h * DHH;
        float inv = 1.f / l[qi];
        o[ob + lane] = o0[qi] * inv;
        o[ob + lane + 32] = o1[qi] * inv;
    }
}

// -------------------- lm head -----------------------------------------------
__global__ __launch_bounds__(256) void logits_kernel(const float* __restrict__ emb,
                                                     const float* __restrict__ xl,
                                                     float* __restrict__ out) {
    int row = blockIdx.x * 8 + (threadIdx.x >> 5);
    int lane = threadIdx.x & 31;
    if (row >= VV) return;
    const float4* er = (const float4*)(emb + (size_t)row * DD);
    const float4* xr = (const float4*)xl;
    float s = 0.f;
#pragma unroll 4
    for (int i = lane; i < DD / 4; i += 32) {
        float4 e = er[i];
        float4 x = xr[i];
        s += e.x * x.x + e.y * x.y + e.z * x.z + e.w * x.w;
    }
#pragma unroll
    for (int off = 16; off; off >>= 1) s += __shfl_xor_sync(0xffffffffu, s, off);
    if (lane == 0) out[row] = s;
}

// ---------------------------------------------------------------------------
extern "C" void kernel_launch(void* const* d_in, const int* in_sizes, int n_in,
                              void* d_out, int out_size) {
    (void)in_sizes; (void)n_in; (void)out_size;
    const int* ids = (const int*)d_in[0];
    const float* emb = (const float*)d_in[1];
    const float* Wq = (const float*)d_in[2];
    const float* Wk = (const float*)d_in[3];
    const float* Wv = (const float*)d_in[4];
    const float* Wo = (const float*)d_in[5];
    const float* Wg = (const float*)d_in[6];
    const float* Wu = (const float*)d_in[7];
    const float* Wd = (const float*)d_in[8];
    const float* attn_norm = (const float*)d_in[9];
    const float* ffn_norm = (const float*)d_in[10];
    const float* norm_out = (const float*)d_in[11];
    float* out = (float*)d_out;

    float *x, *hn, *q, *k, *v, *att, *act, *p, *xl;
    cudaGetSymbolAddress((void**)&x, g_x);
    cudaGetSymbolAddress((void**)&hn, g_hn);
    cudaGetSymbolAddress((void**)&q, g_q);
    cudaGetSymbolAddress((void**)&k, g_k);
    cudaGetSymbolAddress((void**)&v, g_v);
    cudaGetSymbolAddress((void**)&att, g_att);
    cudaGetSymbolAddress((void**)&act, g_act);
    cudaGetSymbolAddress((void**)&p, g_p);
    cudaGetSymbolAddress((void**)&xl, g_xl);

    gather_kernel<<<TT, 256>>>(ids, emb, x);

    for (int l = 0; l < LL; l++) {
        const float* wq = Wq + (size_t)l * DD * DD;
        const float* wk = Wk + (size_t)l * DD * DD;
        const float* wv = Wv + (size_t)l * DD * DD;
        const float* wo = Wo + (size_t)l * DD * DD;
        const float* wg = Wg + (size_t)l * DD * FF;
        const float* wu = Wu + (size_t)l * DD * FF;
        const float* wd = Wd + (size_t)l * FF * DD;

        addnorm_kernel<<<TT, 256>>>(x, p, (l == 0) ? 0 : 4,
                                    attn_norm + (size_t)l * DD, hn, 0);

        qkv_kernel<<<dim3(16, 3), 256>>>(hn, wq, wk, wv, q, k, v);

        attn_kernel<<<dim3(8, HH), 128>>>(q, k, v, att);

        proj_kernel<<<dim3(32, 4), 256>>>(att, wo, p, DD, DD, 4);

        addnorm_kernel<<<TT, 256>>>(x, p, 4, ffn_norm + (size_t)l * DD, hn, 0);

        gateup_kernel<<<FF / 32, 256>>>(hn, wg, wu, act);

        proj_kernel<<<dim3(32, 4), 256>>>(act, wd, p, DD, FF, 4);
    }

    addnorm_kernel<<<1, 256>>>(x, p, 4, norm_out, xl, TT - 1);

    logits_kernel<<<(VV + 7) / 8, 256>>>(emb, xl, out);
}